// round 2
// baseline (speedup 1.0000x reference)
#include <cuda_runtime.h>
#include <cstdint>

#define BSZ 32
#define SEQ_LEN 4096
#define EMBED_DIM 1024
#define PAD_IDX 1
#define SEP_ID 4

// Scratch for computed positions (allocation-free rule: device global).
__device__ int g_pos[BSZ * SEQ_LEN];

// ---------------------------------------------------------------------------
// Kernel 1: positions. One block per batch row, 1024 threads, 4 tokens/thread.
// pos[j] = (no PAD in [0..j]) ? (j - lastSepIdx<=j + 2) : 1
// Scan state: fp = min index of PAD so far (identity INT_MAX),
//             ls = max sep index so far   (identity 0 = virtual sep at 0).
// ---------------------------------------------------------------------------
__global__ __launch_bounds__(1024, 1)
void positions_kernel(const int* __restrict__ tok32) {
    const int row  = blockIdx.x;
    const int t    = threadIdx.x;            // 0..1023
    const int lane = t & 31;
    const int warp = t >> 5;

    __shared__ int s_fp[32];
    __shared__ int s_ls[32];
    __shared__ int s_is64;

    // ---- dtype probe: int64 tokens have zero high words for values <2^31 ----
    if (t == 0) {
        int odd_nonzero = 0;
        #pragma unroll
        for (int k = 1; k < 64; k += 2) odd_nonzero |= tok32[k];
        s_is64 = (odd_nonzero == 0) ? 1 : 0;
    }
    __syncthreads();
    const int is64 = s_is64;

    // ---- load my 4 contiguous tokens ----
    const int base = t * 4;                  // local j within the row
    int tk[4];
    if (is64) {
        const longlong2* p =
            (const longlong2*)((const long long*)tok32 + (size_t)row * SEQ_LEN + base);
        longlong2 a = p[0];
        longlong2 b = p[1];
        tk[0] = (int)a.x; tk[1] = (int)a.y; tk[2] = (int)b.x; tk[3] = (int)b.y;
    } else {
        const int4* p = (const int4*)(tok32 + (size_t)row * SEQ_LEN + base);
        int4 a = p[0];
        tk[0] = a.x; tk[1] = a.y; tk[2] = a.z; tk[3] = a.w;
    }

    // ---- local aggregate over my 4 tokens ----
    int fp = 0x7fffffff;   // first PAD index (min)
    int ls = 0;            // last SEP index (max)
    #pragma unroll
    for (int e = 0; e < 4; e++) {
        int j = base + e;
        if (tk[e] == PAD_IDX) fp = min(fp, j);
        if (tk[e] == SEP_ID)  ls = max(ls, j);
    }

    // ---- inclusive warp scan (min/max) ----
    int ifp = fp, ils = ls;
    #pragma unroll
    for (int d = 1; d < 32; d <<= 1) {
        int ofp = __shfl_up_sync(0xffffffffu, ifp, d);
        int ols = __shfl_up_sync(0xffffffffu, ils, d);
        if (lane >= d) { ifp = min(ifp, ofp); ils = max(ils, ols); }
    }
    if (lane == 31) { s_fp[warp] = ifp; s_ls[warp] = ils; }
    __syncthreads();

    // ---- scan warp aggregates (warp 0) ----
    if (warp == 0) {
        int wfp = s_fp[lane], wls = s_ls[lane];
        #pragma unroll
        for (int d = 1; d < 32; d <<= 1) {
            int ofp = __shfl_up_sync(0xffffffffu, wfp, d);
            int ols = __shfl_up_sync(0xffffffffu, wls, d);
            if (lane >= d) { wfp = min(wfp, ofp); wls = max(wls, ols); }
        }
        s_fp[lane] = wfp; s_ls[lane] = wls;
    }
    __syncthreads();

    // ---- exclusive prefix for this thread ----
    int exfp = 0x7fffffff, exls = 0;
    if (warp > 0) { exfp = s_fp[warp - 1]; exls = s_ls[warp - 1]; }
    // lane-exclusive within warp:
    int lfp = __shfl_up_sync(0xffffffffu, ifp, 1);
    int lls = __shfl_up_sync(0xffffffffu, ils, 1);
    if (lane > 0) { exfp = min(exfp, lfp); exls = max(exls, lls); }

    // ---- finalize my 4 elements (inclusive of current token) ----
    int* out = g_pos + (size_t)row * SEQ_LEN;
    int fpx = exfp, lsx = exls;
    #pragma unroll
    for (int e = 0; e < 4; e++) {
        int j = base + e;
        if (tk[e] == PAD_IDX) fpx = min(fpx, j);
        if (tk[e] == SEP_ID)  lsx = max(lsx, j);
        out[j] = (j < fpx) ? (j - lsx + 2) : 1;
    }
}

// ---------------------------------------------------------------------------
// Kernel 2: gather. One block (256 threads) per output row; each thread
// copies one float4 (1024 floats = 256 float4). Writes perfectly coalesced;
// weights (16.8 MB) reads hit L2.
// ---------------------------------------------------------------------------
__global__ __launch_bounds__(256, 8)
void gather_kernel(const float4* __restrict__ w, float4* __restrict__ out) {
    const int row = blockIdx.x;                    // 0 .. BSZ*SEQ_LEN-1
    const int p   = g_pos[row];                    // uniform per block
    const float4* __restrict__ src = w + (size_t)p * (EMBED_DIM / 4);
    float4* __restrict__ dst = out + (size_t)row * (EMBED_DIM / 4);
    dst[threadIdx.x] = __ldg(&src[threadIdx.x]);
}

extern "C" void kernel_launch(void* const* d_in, const int* in_sizes, int n_in,
                              void* d_out, int out_size) {
    const int*   tokens  = (const int*)d_in[0];     // int32 or int64 (probed)
    const float* weights = (const float*)d_in[1];   // [4098, 1024] f32
    float* out = (float*)d_out;                     // [32, 4096, 1024] f32

    positions_kernel<<<BSZ, 1024>>>(tokens);
    gather_kernel<<<BSZ * SEQ_LEN, 256>>>((const float4*)weights, (float4*)out);
}

// round 3
// speedup vs baseline: 1.4938x; 1.4938x over previous
#include <cuda_runtime.h>
#include <cstdint>

#define BSZ 32
#define SEQ_LEN 4096
#define EMBED_DIM 1024
#define PAD_IDX 1
#define SEP_ID 4

// Scratch for computed positions (allocation-free rule: device global).
__device__ int g_pos[BSZ * SEQ_LEN];

// ---------------------------------------------------------------------------
// Kernel 1: positions. One block per batch row, 1024 threads, 4 tokens/thread.
// pos[j] = (no PAD in [0..j]) ? (j - lastSepIdx<=j + 2) : 1
// Scan state: fp = min index of PAD so far (identity INT_MAX),
//             ls = max sep index so far   (identity 0 = virtual sep at 0).
// ---------------------------------------------------------------------------
__global__ __launch_bounds__(1024, 1)
void positions_kernel(const int* __restrict__ tok32) {
    const int row  = blockIdx.x;
    const int t    = threadIdx.x;            // 0..1023
    const int lane = t & 31;
    const int warp = t >> 5;

    __shared__ int s_fp[32];
    __shared__ int s_ls[32];
    __shared__ int s_is64;

    // ---- dtype probe: int64 tokens have zero high words for values <2^31 ----
    if (t == 0) {
        int odd_nonzero = 0;
        #pragma unroll
        for (int k = 1; k < 64; k += 2) odd_nonzero |= tok32[k];
        s_is64 = (odd_nonzero == 0) ? 1 : 0;
    }
    __syncthreads();
    const int is64 = s_is64;

    // ---- load my 4 contiguous tokens ----
    const int base = t * 4;                  // local j within the row
    int tk[4];
    if (is64) {
        const longlong2* p =
            (const longlong2*)((const long long*)tok32 + (size_t)row * SEQ_LEN + base);
        longlong2 a = p[0];
        longlong2 b = p[1];
        tk[0] = (int)a.x; tk[1] = (int)a.y; tk[2] = (int)b.x; tk[3] = (int)b.y;
    } else {
        const int4* p = (const int4*)(tok32 + (size_t)row * SEQ_LEN + base);
        int4 a = p[0];
        tk[0] = a.x; tk[1] = a.y; tk[2] = a.z; tk[3] = a.w;
    }

    // ---- local aggregate over my 4 tokens ----
    int fp = 0x7fffffff;   // first PAD index (min)
    int ls = 0;            // last SEP index (max)
    #pragma unroll
    for (int e = 0; e < 4; e++) {
        int j = base + e;
        if (tk[e] == PAD_IDX) fp = min(fp, j);
        if (tk[e] == SEP_ID)  ls = max(ls, j);
    }

    // ---- inclusive warp scan (min/max) ----
    int ifp = fp, ils = ls;
    #pragma unroll
    for (int d = 1; d < 32; d <<= 1) {
        int ofp = __shfl_up_sync(0xffffffffu, ifp, d);
        int ols = __shfl_up_sync(0xffffffffu, ils, d);
        if (lane >= d) { ifp = min(ifp, ofp); ils = max(ils, ols); }
    }
    if (lane == 31) { s_fp[warp] = ifp; s_ls[warp] = ils; }
    __syncthreads();

    // ---- scan warp aggregates (warp 0) ----
    if (warp == 0) {
        int wfp = s_fp[lane], wls = s_ls[lane];
        #pragma unroll
        for (int d = 1; d < 32; d <<= 1) {
            int ofp = __shfl_up_sync(0xffffffffu, wfp, d);
            int ols = __shfl_up_sync(0xffffffffu, wls, d);
            if (lane >= d) { wfp = min(wfp, ofp); wls = max(wls, ols); }
        }
        s_fp[lane] = wfp; s_ls[lane] = wls;
    }
    __syncthreads();

    // ---- exclusive prefix for this thread ----
    int exfp = 0x7fffffff, exls = 0;
    if (warp > 0) { exfp = s_fp[warp - 1]; exls = s_ls[warp - 1]; }
    // lane-exclusive within warp:
    int lfp = __shfl_up_sync(0xffffffffu, ifp, 1);
    int lls = __shfl_up_sync(0xffffffffu, ils, 1);
    if (lane > 0) { exfp = min(exfp, lfp); exls = max(exls, lls); }

    // ---- finalize my 4 elements (inclusive of current token) ----
    int* out = g_pos + (size_t)row * SEQ_LEN;
    int fpx = exfp, lsx = exls;
    #pragma unroll
    for (int e = 0; e < 4; e++) {
        int j = base + e;
        if (tk[e] == PAD_IDX) fpx = min(fpx, j);
        if (tk[e] == SEP_ID)  lsx = max(lsx, j);
        out[j] = (j < fpx) ? (j - lsx + 2) : 1;
    }
}

// ---------------------------------------------------------------------------
// Kernel 2: gather v2. 4 rows per block of 256 threads. Thread t copies
// float4 column t of each row: 4 independent LDG.128 (MLP=4) followed by
// 4 STG.128 with evict-first (__stcs) so the 512MB output stream doesn't
// evict the 16.8MB weights table from L2.
// ---------------------------------------------------------------------------
#define ROWS_PER_BLK 4
#define F4_PER_ROW (EMBED_DIM / 4)   // 256

__global__ __launch_bounds__(256, 8)
void gather_kernel(const float4* __restrict__ w, float4* __restrict__ out) {
    const int row0 = blockIdx.x * ROWS_PER_BLK;
    const int t    = threadIdx.x;

    const int p0 = g_pos[row0 + 0];
    const int p1 = g_pos[row0 + 1];
    const int p2 = g_pos[row0 + 2];
    const int p3 = g_pos[row0 + 3];

    // 4 independent loads in flight (L2 hits after first touch)
    float4 v0 = __ldg(w + (size_t)p0 * F4_PER_ROW + t);
    float4 v1 = __ldg(w + (size_t)p1 * F4_PER_ROW + t);
    float4 v2 = __ldg(w + (size_t)p2 * F4_PER_ROW + t);
    float4 v3 = __ldg(w + (size_t)p3 * F4_PER_ROW + t);

    float4* dst = out + (size_t)row0 * F4_PER_ROW + t;
    __stcs(dst + 0 * F4_PER_ROW, v0);
    __stcs(dst + 1 * F4_PER_ROW, v1);
    __stcs(dst + 2 * F4_PER_ROW, v2);
    __stcs(dst + 3 * F4_PER_ROW, v3);
}

extern "C" void kernel_launch(void* const* d_in, const int* in_sizes, int n_in,
                              void* d_out, int out_size) {
    const int*   tokens  = (const int*)d_in[0];     // int32 or int64 (probed)
    const float* weights = (const float*)d_in[1];   // [4098, 1024] f32
    float* out = (float*)d_out;                     // [32, 4096, 1024] f32

    positions_kernel<<<BSZ, 1024>>>(tokens);
    gather_kernel<<<(BSZ * SEQ_LEN) / ROWS_PER_BLK, 256>>>(
        (const float4*)weights, (float4*)out);
}